// round 15
// baseline (speedup 1.0000x reference)
#include <cuda_runtime.h>
#include <cstdint>

// Dykstra alternating projection, n=4096, up to 20 iterations.
//   Xp = X + (1/n + s/n^2) - row_i/n - col_j/n ;  X <- relu(Xp)
//   freeze X once min(Xp) >= 0  (relu(Xp)==Xp in that case)
//
// R14 -> R15: persistent-kernel attack. Sweep is ~HBM-bound (~7TB/s
// combined); remaining losses are launch gaps (21 kernels), the serial
// reduce0 pre-pass, and per-kernel tail imbalance (512 blocks / 148 SMs).
// One launch: 592 co-resident blocks (4/SM enforced), hand-rolled grid
// barrier, work-stealing 1-row chunks (atomic tickets, prefetched) for
// ~1% tail, prologue folded in as phase 0. Col sums keep the proven TMA
// bulk-reduce + triple buffering. evict_last hints reverted (R14 regression).

#define NDIM 4096
#define NTHREADS 256
#define NWARPS (NTHREADS / 32)
#define MAXIT 20
#define F4_PER_ROW (NDIM / 4)          // 1024
#define FPT (F4_PER_ROW / NTHREADS)    // 4 float4 per thread per row
#define NBLOCKS 592                    // 148 SMs x 4 blocks (all co-resident)
#define COL_BYTES (NDIM * 4)

__device__ float  g_row[NDIM];              // row sums (owner-exclusive)
__device__ float4 g_col[3][F4_PER_ROW];     // col sums, triple-buffered
__device__ float  g_total[MAXIT + 1];
__device__ int    g_neg[MAXIT];
__device__ unsigned g_ticket[MAXIT + 1];    // work-stealing counters per phase
__device__ unsigned g_bar_count;
__device__ unsigned g_bar_gen;

__global__ void init_kernel() {
    int t = threadIdx.x;
    for (int i = t; i < F4_PER_ROW; i += NTHREADS) {
        g_col[0][i] = make_float4(0.f, 0.f, 0.f, 0.f);
        g_col[1][i] = make_float4(0.f, 0.f, 0.f, 0.f);
    }
    if (t <= MAXIT) { g_total[t] = 0.f; g_ticket[t] = 0u; }
    if (t < MAXIT)  g_neg[t] = 0;
    if (t == 0) { g_bar_count = 0u; g_bar_gen = 0u; }
}

__device__ __forceinline__ float warpReduceSum(float v) {
    #pragma unroll
    for (int o = 16; o > 0; o >>= 1) v += __shfl_down_sync(0xffffffffu, v, o);
    return v;
}

// Grid-wide barrier (CG grid.sync pattern): generation counter with
// acquire/release; intra-block ordering via the surrounding __syncthreads.
__device__ __forceinline__ void grid_barrier() {
    __syncthreads();
    if (threadIdx.x == 0) {
        __threadfence();
        unsigned gen;
        asm volatile("ld.acquire.gpu.u32 %0, [%1];" : "=r"(gen) : "l"(&g_bar_gen));
        if (atomicAdd(&g_bar_count, 1u) == NBLOCKS - 1) {
            g_bar_count = 0u;
            asm volatile("st.release.gpu.u32 [%0], %1;"
                         :: "l"(&g_bar_gen), "r"(gen + 1u) : "memory");
        } else {
            unsigned cur;
            do {
                __nanosleep(64);
                asm volatile("ld.acquire.gpu.u32 %0, [%1];" : "=r"(cur) : "l"(&g_bar_gen));
            } while (cur == gen);
        }
    }
    __syncthreads();
}

// One bulk reduce-add of a 16KB SMEM buffer into gmem (async-proxy, sm_90+).
__device__ __forceinline__ void bulk_reduce_add_f32(void* gdst, const void* smem_src) {
    if (threadIdx.x == 0) {
        asm volatile("fence.proxy.async.shared::cta;" ::: "memory");
        uint32_t saddr;
        asm volatile("{\n\t.reg .u64 t;\n\tcvta.to.shared.u64 t, %1;\n\tcvt.u32.u64 %0, t;\n\t}"
                     : "=r"(saddr) : "l"(smem_src));
        asm volatile("{\n\t.reg .u64 g;\n\tcvta.to.global.u64 g, %0;\n\t"
                     "cp.reduce.async.bulk.global.shared::cta.bulk_group.add.f32 [g], [%1], %2;\n\t}"
                     :: "l"((uint64_t)gdst), "r"(saddr), "r"((uint32_t)COL_BYTES) : "memory");
        asm volatile("cp.async.bulk.commit_group;" ::: "memory");
        asm volatile("cp.async.bulk.wait_group 0;" ::: "memory");
    }
}

__global__ __launch_bounds__(NTHREADS, 4)
void persist_kernel(const float* __restrict__ X, float* __restrict__ out,
                    const int* __restrict__ max_iters) {
    __shared__ __align__(16) float4 s_colpart[F4_PER_ROW];   // 16KB
    __shared__ __align__(16) float4 s_cvn[F4_PER_ROW];       // 16KB
    __shared__ float s_part[2][NWARPS];
    __shared__ unsigned s_chunk[2];
    int t = threadIdx.x;
    int lane = t & 31, wid = t >> 5;
    const float inv_n = 1.0f / NDIM;

    int maxit = *max_iters;
    if (maxit > MAXIT) maxit = MAXIT;
    if (maxit <= 0) {   // output = input (never hit for 20)
        const float4* xi = (const float4*)X;
        float4* yo = (float4*)out;
        for (size_t i = (size_t)blockIdx.x * NTHREADS + t;
             i < (size_t)NDIM * F4_PER_ROW; i += (size_t)NBLOCKS * NTHREADS)
            yo[i] = xi[i];
        return;
    }

    // ---- Phase 0 (prologue): row/col/total sums of the initial X ----
    {
        const float4* xi = (const float4*)X;
        float4 cacc[FPT];
        #pragma unroll
        for (int g = 0; g < FPT; g++) cacc[g] = make_float4(0.f, 0.f, 0.f, 0.f);
        if (t == 0) s_chunk[0] = atomicAdd(&g_ticket[0], 1u);
        __syncthreads();
        int par = 0;
        unsigned row = s_chunk[0];
        while (row < NDIM) {
            if (t == 0) s_chunk[par ^ 1] = atomicAdd(&g_ticket[0], 1u);
            const float4* xr = xi + (size_t)row * F4_PER_ROW;
            float rp = 0.f;
            #pragma unroll
            for (int g = 0; g < FPT; g++) {
                float4 v = xr[t + NTHREADS * g];
                rp += (v.x + v.y) + (v.z + v.w);
                cacc[g].x += v.x; cacc[g].y += v.y; cacc[g].z += v.z; cacc[g].w += v.w;
            }
            float rs = warpReduceSum(rp);
            if (lane == 0) s_part[par][wid] = rs;
            __syncthreads();
            if (t == 0) {
                float s = 0.f;
                #pragma unroll
                for (int w = 0; w < NWARPS; w++) s += s_part[par][w];
                g_row[row] = s;
                atomicAdd(&g_total[0], s);
            }
            par ^= 1;
            row = s_chunk[par];
        }
        #pragma unroll
        for (int g = 0; g < FPT; g++) s_colpart[t + NTHREADS * g] = cacc[g];
        __syncthreads();
        bulk_reduce_add_f32(&g_col[0][0], s_colpart);
        grid_barrier();
    }

    // ---- Iterations ----
    for (int k = 0; k < maxit; k++) {
        int rdc = k % 3, wrc = (k + 1) % 3, zc = (k + 2) % 3;
        const float4* xi = (k == 0) ? (const float4*)X : (const float4*)out;
        float4* yo = (float4*)out;

        // Stage pre-scaled col values into SMEM.
        #pragma unroll
        for (int g = 0; g < FPT; g++) {
            float4 cv = g_col[rdc][t + NTHREADS * g];
            s_cvn[t + NTHREADS * g] =
                make_float4(cv.x * inv_n, cv.y * inv_n, cv.z * inv_n, cv.w * inv_n);
        }
        float total = g_total[k];
        float cc = inv_n + total * inv_n * inv_n;

        float4 cacc[FPT];
        #pragma unroll
        for (int g = 0; g < FPT; g++) cacc[g] = make_float4(0.f, 0.f, 0.f, 0.f);
        bool neg = false;

        if (t == 0) s_chunk[0] = atomicAdd(&g_ticket[k + 1], 1u);
        __syncthreads();
        int par = 0;
        unsigned row = s_chunk[0];
        while (row < NDIM) {
            if (t == 0) s_chunk[par ^ 1] = atomicAdd(&g_ticket[k + 1], 1u);
            float a = cc - g_row[row] * inv_n;      // uniform load (old value)
            const float4* xr = xi + (size_t)row * F4_PER_ROW;
            float4*       yr = yo + (size_t)row * F4_PER_ROW;
            float rp = 0.f;
            #pragma unroll
            for (int g = 0; g < FPT; g++) {
                int i = t + NTHREADS * g;
                float4 v = xr[i];
                float4 cvn = s_cvn[i];
                float4 xp;
                xp.x = v.x + a - cvn.x;
                xp.y = v.y + a - cvn.y;
                xp.z = v.z + a - cvn.z;
                xp.w = v.w + a - cvn.w;
                float mn = fminf(fminf(xp.x, xp.y), fminf(xp.z, xp.w));
                neg = neg || (mn < 0.f);
                float4 y;
                y.x = fmaxf(xp.x, 0.f); y.y = fmaxf(xp.y, 0.f);
                y.z = fmaxf(xp.z, 0.f); y.w = fmaxf(xp.w, 0.f);
                yr[i] = y;
                rp += (y.x + y.y) + (y.z + y.w);
                cacc[g].x += y.x; cacc[g].y += y.y; cacc[g].z += y.z; cacc[g].w += y.w;
            }
            float rs = warpReduceSum(rp);
            if (lane == 0) s_part[par][wid] = rs;
            __syncthreads();   // also orders: all threads read g_row[row] above
            if (t == 0) {
                float s = 0.f;
                #pragma unroll
                for (int w = 0; w < NWARPS; w++) s += s_part[par][w];
                g_row[row] = s;                      // owner-exclusive
                atomicAdd(&g_total[k + 1], s);
            }
            par ^= 1;
            row = s_chunk[par];
        }

        // End of iteration: neg flag, col bulk-reduce, zero the k+2 buffer.
        #pragma unroll
        for (int g = 0; g < FPT; g++) s_colpart[t + NTHREADS * g] = cacc[g];
        if (__syncthreads_or(neg ? 1 : 0)) {
            if (t == 0) g_neg[k] = 1;
        }
        bulk_reduce_add_f32(&g_col[wrc][0], s_colpart);
        if (blockIdx.x < 512 && t < 2)
            g_col[zc][blockIdx.x * 2 + t] = make_float4(0.f, 0.f, 0.f, 0.f);

        grid_barrier();

        // Converged? (iteration k produced all-nonneg Xp -> out == Xp final)
        if (g_neg[k] == 0) break;   // uniform across all blocks
    }
}

extern "C" void kernel_launch(void* const* d_in, const int* in_sizes, int n_in,
                              void* d_out, int out_size) {
    const float* X = (const float*)d_in[0];
    const int* max_iters = (const int*)d_in[1];
    float* out = (float*)d_out;
    (void)in_sizes; (void)n_in; (void)out_size;

    init_kernel<<<1, NTHREADS>>>();
    persist_kernel<<<NBLOCKS, NTHREADS>>>(X, out, max_iters);
}

// round 16
// speedup vs baseline: 1.2041x; 1.2041x over previous
#include <cuda_runtime.h>
#include <cstdint>

// Dykstra alternating projection, n=4096, up to 20 iterations.
//   Xp = X + (1/n + s/n^2) - row_i/n - col_j/n ;  X <- relu(Xp)
//   freeze X once min(Xp) >= 0  (relu(Xp)==Xp in that case)
//
// R15 -> R16: lazy checkpointing. Per-iter time (18.8us for 128MB) sits at
// the LTS chip cap -> only byte reduction helps. X_{k+1} is recomputable
// from X_k + per-iteration vectors (A_k[i], B_k[j]), so materialize X only
// every 2nd iteration: even passes = read-only (64MB, 1 level, sums only);
// odd passes = read+write (128MB, 2 levels). Traffic 2.62GB -> ~1.95GB.
// Sums per iteration stored in per-level arrays (g_rowsum/g_colsum/g_total);
// col sums still via the proven TMA bulk-reduce (destinations pre-zeroed).

#define NDIM 4096
#define RPB 8
#define NBLK (NDIM / RPB)             // 512
#define NTHREADS 256
#define NWARPS (NTHREADS / 32)
#define MAXIT 20
#define F4_PER_ROW (NDIM / 4)         // 1024
#define FPT (F4_PER_ROW / NTHREADS)   // 4
#define COL_BYTES (NDIM * 4)

__device__ float g_rowsum[MAXIT + 1][NDIM];
__device__ float g_colsum[MAXIT + 1][NDIM];
__device__ float g_total[MAXIT + 1];
__device__ int   g_neg[MAXIT];
__device__ int   g_mat;               // post-freeze materialization done

__global__ void init_kernel() {     // grid 84: zero 21*1024 f4 of colsum
    int i = blockIdx.x * NTHREADS + threadIdx.x;
    ((float4*)g_colsum)[i] = make_float4(0.f, 0.f, 0.f, 0.f);
    if (blockIdx.x == 0) {
        int t = threadIdx.x;
        if (t <= MAXIT) g_total[t] = 0.f;
        if (t < MAXIT)  g_neg[t] = 0;
        if (t == 0)     g_mat = 0;
    }
}

__device__ __forceinline__ float warpReduceSum(float v) {
    #pragma unroll
    for (int o = 16; o > 0; o >>= 1) v += __shfl_down_sync(0xffffffffu, v, o);
    return v;
}

__device__ __forceinline__ void bulk_reduce_add_f32(void* gdst, const void* smem_src) {
    if (threadIdx.x == 0) {
        asm volatile("fence.proxy.async.shared::cta;" ::: "memory");
        uint32_t saddr;
        asm volatile("{\n\t.reg .u64 t;\n\tcvta.to.shared.u64 t, %1;\n\tcvt.u32.u64 %0, t;\n\t}"
                     : "=r"(saddr) : "l"(smem_src));
        asm volatile("{\n\t.reg .u64 g;\n\tcvta.to.global.u64 g, %0;\n\t"
                     "cp.reduce.async.bulk.global.shared::cta.bulk_group.add.f32 [g], [%1], %2;\n\t}"
                     :: "l"((uint64_t)gdst), "r"(saddr), "r"((uint32_t)COL_BYTES) : "memory");
        asm volatile("cp.async.bulk.commit_group;" ::: "memory");
        asm volatile("cp.async.bulk.wait_group 0;" ::: "memory");
    }
}

// Prologue: row/col/total sums of the initial X.
__global__ __launch_bounds__(NTHREADS, 4)
void reduce0_kernel(const float* __restrict__ X) {
    __shared__ __align__(16) float s_colpart[NDIM];   // 16KB
    __shared__ float s_part[NWARPS][RPB];
    int t = threadIdx.x, lane = t & 31, wid = t >> 5;
    int row0 = blockIdx.x * RPB;

    float4 cacc[FPT];
    #pragma unroll
    for (int g = 0; g < FPT; g++) cacc[g] = make_float4(0.f, 0.f, 0.f, 0.f);
    #pragma unroll
    for (int r = 0; r < RPB; r++) {
        const float4* xr = (const float4*)(X + (size_t)(row0 + r) * NDIM);
        float rp = 0.f;
        #pragma unroll
        for (int g = 0; g < FPT; g++) {
            float4 v = xr[t + NTHREADS * g];
            rp += (v.x + v.y) + (v.z + v.w);
            cacc[g].x += v.x; cacc[g].y += v.y; cacc[g].z += v.z; cacc[g].w += v.w;
        }
        float rs = warpReduceSum(rp);
        if (lane == 0) s_part[wid][r] = rs;
    }
    #pragma unroll
    for (int g = 0; g < FPT; g++)
        ((float4*)s_colpart)[t + NTHREADS * g] = cacc[g];
    __syncthreads();
    if (t < RPB) {
        float rs = 0.f;
        #pragma unroll
        for (int w = 0; w < NWARPS; w++) rs += s_part[w][t];
        g_rowsum[0][row0 + t] = rs;
        atomicAdd(&g_total[0], rs);
    }
    bulk_reduce_add_f32(&g_colsum[0][0], s_colpart);
}

// Pass k: advance one iteration level. Even k: read-only (1 level, sums of
// X_{k+1}). Odd k: 2 levels from checkpoint X_{k-1}, writes X_{k+1}.
// Invariant at entry: `out` holds X_{k & ~1} (checkpoint); base 0 = input X.
__global__ __launch_bounds__(NTHREADS, 4)
void pass_kernel(const float* __restrict__ X, float* __restrict__ out,
                 const int* __restrict__ max_iters, int k) {
    __shared__ __align__(16) float s_b0[NDIM];   // level `base` B; reused as colpart
    __shared__ __align__(16) float s_b1[NDIM];   // level `k` B (always)
    __shared__ float s_part[NWARPS][RPB];
    __shared__ float s_a0[RPB], s_a1[RPB];
    __shared__ int s_conv, s_mi, s_mat;
    int t = threadIdx.x, lane = t & 31, wid = t >> 5;
    int row0 = blockIdx.x * RPB;
    const float inv_n = 1.0f / NDIM;

    if (t < 32) {
        int z = (t < k) ? (g_neg[t] == 0) : 0;
        unsigned m = __ballot_sync(0xffffffffu, z);
        if (t == 0) {
            s_conv = m ? (__ffs(m) - 1) : 999;
            s_mi = *max_iters;
            s_mat = g_mat;
        }
    }
    __syncthreads();
    int mi = s_mi, conv = s_conv;

    if (conv < k || k >= mi) {
        // Frozen: final X = X_f. out holds X_{k&~1}; writes after freeze never
        // happened, so out = X_{f-1} (f odd) or X_f (f even>0).
        int f = (conv < k) ? conv + 1 : mi;
        bool have = ((f & 1) == 0) && (f > 0);
        if (have || s_mat) return;
        if (f == 0) {   // output = input
            const float4* xi = (const float4*)X;
            float4* yo = (float4*)out;
            #pragma unroll
            for (int r = 0; r < RPB; r++)
                #pragma unroll
                for (int g = 0; g < FPT; g++) {
                    size_t i = (size_t)(row0 + r) * F4_PER_ROW + t + NTHREADS * g;
                    yo[i] = xi[i];
                }
        } else {        // apply level f-1 to out (holds X_{f-1}) in place
            int lev = f - 1;
            #pragma unroll
            for (int g = 0; g < FPT; g++) {
                int i = t + NTHREADS * g;
                float4 cv = ((const float4*)g_colsum[lev])[i];
                ((float4*)s_b1)[i] = make_float4(cv.x * inv_n, cv.y * inv_n,
                                                 cv.z * inv_n, cv.w * inv_n);
            }
            if (t < RPB) {
                float c = inv_n + g_total[lev] * inv_n * inv_n;
                s_a1[t] = c - g_rowsum[lev][row0 + t] * inv_n;
            }
            __syncthreads();
            float4* yo = (float4*)out;
            #pragma unroll
            for (int r = 0; r < RPB; r++) {
                float a = s_a1[r];
                #pragma unroll
                for (int g = 0; g < FPT; g++) {
                    size_t i = (size_t)(row0 + r) * F4_PER_ROW + t + NTHREADS * g;
                    float4 v = yo[i];
                    float4 b = ((const float4*)s_b1)[t + NTHREADS * g];
                    v.x = fmaxf((v.x + a) - b.x, 0.f);
                    v.y = fmaxf((v.y + a) - b.y, 0.f);
                    v.z = fmaxf((v.z + a) - b.z, 0.f);
                    v.w = fmaxf((v.w + a) - b.w, 0.f);
                    yo[i] = v;
                }
            }
        }
        if (t == 0) g_mat = 1;
        return;
    }

    // ---- normal path ----
    const int base = k & ~1;
    const bool two = (k & 1) != 0;        // two levels <=> write pass

    // Load B tables (pre-scaled) and per-row A constants.
    #pragma unroll
    for (int g = 0; g < FPT; g++) {
        int i = t + NTHREADS * g;
        float4 cv = ((const float4*)g_colsum[k])[i];
        ((float4*)s_b1)[i] = make_float4(cv.x * inv_n, cv.y * inv_n,
                                         cv.z * inv_n, cv.w * inv_n);
        if (two) {
            float4 c0 = ((const float4*)g_colsum[base])[i];
            ((float4*)s_b0)[i] = make_float4(c0.x * inv_n, c0.y * inv_n,
                                             c0.z * inv_n, c0.w * inv_n);
        }
    }
    if (t < RPB) {
        float c1 = inv_n + g_total[k] * inv_n * inv_n;
        s_a1[t] = c1 - g_rowsum[k][row0 + t] * inv_n;
        if (two) {
            float c0 = inv_n + g_total[base] * inv_n * inv_n;
            s_a0[t] = c0 - g_rowsum[base][row0 + t] * inv_n;
        }
    }
    __syncthreads();

    const float4* xi = (base == 0) ? (const float4*)X : (const float4*)out;
    float4* yo = (float4*)out;

    float4 cacc[FPT];
    #pragma unroll
    for (int g = 0; g < FPT; g++) cacc[g] = make_float4(0.f, 0.f, 0.f, 0.f);
    bool neg = false;

    #pragma unroll
    for (int r = 0; r < RPB; r++) {
        float a1 = s_a1[r];
        float a0 = two ? s_a0[r] : 0.f;
        float rp = 0.f;
        #pragma unroll
        for (int g = 0; g < FPT; g++) {
            int j = t + NTHREADS * g;
            size_t i = (size_t)(row0 + r) * F4_PER_ROW + j;
            float4 v = xi[i];
            if (two) {   // level `base` first (no neg check: set last pass)
                float4 b0 = ((const float4*)s_b0)[j];
                v.x = fmaxf((v.x + a0) - b0.x, 0.f);
                v.y = fmaxf((v.y + a0) - b0.y, 0.f);
                v.z = fmaxf((v.z + a0) - b0.z, 0.f);
                v.w = fmaxf((v.w + a0) - b0.w, 0.f);
            }
            float4 b1 = ((const float4*)s_b1)[j];
            float4 xp;
            xp.x = (v.x + a1) - b1.x;
            xp.y = (v.y + a1) - b1.y;
            xp.z = (v.z + a1) - b1.z;
            xp.w = (v.w + a1) - b1.w;
            float mn = fminf(fminf(xp.x, xp.y), fminf(xp.z, xp.w));
            neg = neg || (mn < 0.f);
            float4 y;
            y.x = fmaxf(xp.x, 0.f); y.y = fmaxf(xp.y, 0.f);
            y.z = fmaxf(xp.z, 0.f); y.w = fmaxf(xp.w, 0.f);
            if (two) yo[i] = y;                 // materialize X_{k+1}
            rp += (y.x + y.y) + (y.z + y.w);
            cacc[g].x += y.x; cacc[g].y += y.y; cacc[g].z += y.z; cacc[g].w += y.w;
        }
        float rs = warpReduceSum(rp);
        if (lane == 0) s_part[wid][r] = rs;
    }

    __syncthreads();                    // all s_b0 reads done; s_part ready
    // Stage col partials into s_b0 (union with colpart).
    #pragma unroll
    for (int g = 0; g < FPT; g++)
        ((float4*)s_b0)[t + NTHREADS * g] = cacc[g];
    if (t < RPB) {
        float rs = 0.f;
        #pragma unroll
        for (int w = 0; w < NWARPS; w++) rs += s_part[w][t];
        g_rowsum[k + 1][row0 + t] = rs;          // block-exclusive
        atomicAdd(&g_total[k + 1], rs);
    }
    if (__syncthreads_or(neg ? 1 : 0)) {
        if (t == 0) g_neg[k] = 1;
    }
    bulk_reduce_add_f32(&g_colsum[k + 1][0], s_b0);
}

extern "C" void kernel_launch(void* const* d_in, const int* in_sizes, int n_in,
                              void* d_out, int out_size) {
    const float* X = (const float*)d_in[0];
    const int* max_iters = (const int*)d_in[1];
    float* out = (float*)d_out;
    (void)in_sizes; (void)n_in; (void)out_size;

    init_kernel<<<(MAXIT + 1) * F4_PER_ROW / NTHREADS, NTHREADS>>>();  // 84 blocks
    reduce0_kernel<<<NBLK, NTHREADS>>>(X);
    for (int k = 0; k < MAXIT; k++)
        pass_kernel<<<NBLK, NTHREADS>>>(X, out, max_iters, k);
}

// round 17
// speedup vs baseline: 1.2512x; 1.0391x over previous
#include <cuda_runtime.h>
#include <cstdint>

// Dykstra alternating projection, n=4096, up to 20 iterations.
//   Xp = X + (1/n + s/n^2) - row_i/n - col_j/n ;  X <- relu(Xp)
//   freeze X once min(Xp) >= 0  (relu(Xp)==Xp in that case)
//
// R16 -> R17: wave-quantization fix. 512 blocks over 148 SMs x 4 slots =
// 86.5% wave efficiency (SMs drawing 4 sequential blocks gate the kernel
// while 3-block SMs idle). Grid = 592 = exactly one wave; blocks own 6 or 7
// rows (544x7 + 48x6 = 4096) -> ~99% efficiency. Rest identical to R16
// champion: period-2 lazy checkpointing (even pass read-only sums, odd pass
// 2-level apply + write), TMA bulk-reduce col sums, per-level sum arrays.

#define NDIM 4096
#define MAXRPB 7
#define NBLK 592                      // 148 SMs x 4 co-resident blocks
#define NTHREADS 256
#define NWARPS (NTHREADS / 32)
#define MAXIT 20
#define F4_PER_ROW (NDIM / 4)         // 1024
#define FPT (F4_PER_ROW / NTHREADS)   // 4
#define COL_BYTES (NDIM * 4)

__device__ float g_rowsum[MAXIT + 1][NDIM];
__device__ float g_colsum[MAXIT + 1][NDIM];
__device__ float g_total[MAXIT + 1];
__device__ int   g_neg[MAXIT];
__device__ int   g_mat;               // post-freeze materialization done

__global__ void init_kernel() {     // grid 84: zero 21*1024 f4 of colsum
    int i = blockIdx.x * NTHREADS + threadIdx.x;
    ((float4*)g_colsum)[i] = make_float4(0.f, 0.f, 0.f, 0.f);
    if (blockIdx.x == 0) {
        int t = threadIdx.x;
        if (t <= MAXIT) g_total[t] = 0.f;
        if (t < MAXIT)  g_neg[t] = 0;
        if (t == 0)     g_mat = 0;
    }
}

__device__ __forceinline__ float warpReduceSum(float v) {
    #pragma unroll
    for (int o = 16; o > 0; o >>= 1) v += __shfl_down_sync(0xffffffffu, v, o);
    return v;
}

__device__ __forceinline__ void bulk_reduce_add_f32(void* gdst, const void* smem_src) {
    if (threadIdx.x == 0) {
        asm volatile("fence.proxy.async.shared::cta;" ::: "memory");
        uint32_t saddr;
        asm volatile("{\n\t.reg .u64 t;\n\tcvta.to.shared.u64 t, %1;\n\tcvt.u32.u64 %0, t;\n\t}"
                     : "=r"(saddr) : "l"(smem_src));
        asm volatile("{\n\t.reg .u64 g;\n\tcvta.to.global.u64 g, %0;\n\t"
                     "cp.reduce.async.bulk.global.shared::cta.bulk_group.add.f32 [g], [%1], %2;\n\t}"
                     :: "l"((uint64_t)gdst), "r"(saddr), "r"((uint32_t)COL_BYTES) : "memory");
        asm volatile("cp.async.bulk.commit_group;" ::: "memory");
        asm volatile("cp.async.bulk.wait_group 0;" ::: "memory");
    }
}

// Block's row range: [bid*4096/592, (bid+1)*4096/592) -> 6 or 7 rows.
__device__ __forceinline__ void block_rows(int bid, int& row0, int& nrows) {
    row0 = (bid * NDIM) / NBLK;
    int row1 = ((bid + 1) * NDIM) / NBLK;
    nrows = row1 - row0;
}

// Prologue: row/col/total sums of the initial X.
__global__ __launch_bounds__(NTHREADS, 4)
void reduce0_kernel(const float* __restrict__ X) {
    __shared__ __align__(16) float s_colpart[NDIM];   // 16KB
    __shared__ float s_part[NWARPS][MAXRPB];
    int t = threadIdx.x, lane = t & 31, wid = t >> 5;
    int row0, nrows;
    block_rows(blockIdx.x, row0, nrows);

    float4 cacc[FPT];
    #pragma unroll
    for (int g = 0; g < FPT; g++) cacc[g] = make_float4(0.f, 0.f, 0.f, 0.f);
    #pragma unroll
    for (int r = 0; r < MAXRPB; r++) {
        if (r < nrows) {
            const float4* xr = (const float4*)(X + (size_t)(row0 + r) * NDIM);
            float rp = 0.f;
            #pragma unroll
            for (int g = 0; g < FPT; g++) {
                float4 v = xr[t + NTHREADS * g];
                rp += (v.x + v.y) + (v.z + v.w);
                cacc[g].x += v.x; cacc[g].y += v.y; cacc[g].z += v.z; cacc[g].w += v.w;
            }
            float rs = warpReduceSum(rp);
            if (lane == 0) s_part[wid][r] = rs;
        }
    }
    #pragma unroll
    for (int g = 0; g < FPT; g++)
        ((float4*)s_colpart)[t + NTHREADS * g] = cacc[g];
    __syncthreads();
    if (t < nrows) {
        float rs = 0.f;
        #pragma unroll
        for (int w = 0; w < NWARPS; w++) rs += s_part[w][t];
        g_rowsum[0][row0 + t] = rs;
        atomicAdd(&g_total[0], rs);
    }
    bulk_reduce_add_f32(&g_colsum[0][0], s_colpart);
}

// Pass k. Even k: read-only (1 level, sums of X_{k+1}). Odd k: 2 levels from
// checkpoint X_{k-1}, writes X_{k+1}. `out` holds X_{k & ~1}; base 0 = X.
__global__ __launch_bounds__(NTHREADS, 4)
void pass_kernel(const float* __restrict__ X, float* __restrict__ out,
                 const int* __restrict__ max_iters, int k) {
    __shared__ __align__(16) float s_b0[NDIM];   // level `base` B; reused as colpart
    __shared__ __align__(16) float s_b1[NDIM];   // level `k` B
    __shared__ float s_part[NWARPS][MAXRPB];
    __shared__ float s_a0[MAXRPB], s_a1[MAXRPB];
    __shared__ int s_conv, s_mi, s_mat;
    int t = threadIdx.x, lane = t & 31, wid = t >> 5;
    int row0, nrows;
    block_rows(blockIdx.x, row0, nrows);
    const float inv_n = 1.0f / NDIM;

    if (t < 32) {
        int z = (t < k) ? (g_neg[t] == 0) : 0;
        unsigned m = __ballot_sync(0xffffffffu, z);
        if (t == 0) {
            s_conv = m ? (__ffs(m) - 1) : 999;
            s_mi = *max_iters;
            s_mat = g_mat;
        }
    }
    __syncthreads();
    int mi = s_mi, conv = s_conv;

    if (conv < k || k >= mi) {
        // Frozen: final X = X_f. out holds X_{k&~1} = X_{f-1} (f odd) or X_f.
        int f = (conv < k) ? conv + 1 : mi;
        bool have = ((f & 1) == 0) && (f > 0);
        if (have || s_mat) return;
        if (f == 0) {   // output = input
            const float4* xi = (const float4*)X;
            float4* yo = (float4*)out;
            #pragma unroll
            for (int r = 0; r < MAXRPB; r++)
                if (r < nrows)
                    #pragma unroll
                    for (int g = 0; g < FPT; g++) {
                        size_t i = (size_t)(row0 + r) * F4_PER_ROW + t + NTHREADS * g;
                        yo[i] = xi[i];
                    }
        } else {        // apply level f-1 to out (holds X_{f-1}) in place
            int lev = f - 1;
            #pragma unroll
            for (int g = 0; g < FPT; g++) {
                int i = t + NTHREADS * g;
                float4 cv = ((const float4*)g_colsum[lev])[i];
                ((float4*)s_b1)[i] = make_float4(cv.x * inv_n, cv.y * inv_n,
                                                 cv.z * inv_n, cv.w * inv_n);
            }
            if (t < nrows) {
                float c = inv_n + g_total[lev] * inv_n * inv_n;
                s_a1[t] = c - g_rowsum[lev][row0 + t] * inv_n;
            }
            __syncthreads();
            float4* yo = (float4*)out;
            #pragma unroll
            for (int r = 0; r < MAXRPB; r++) {
                if (r < nrows) {
                    float a = s_a1[r];
                    #pragma unroll
                    for (int g = 0; g < FPT; g++) {
                        size_t i = (size_t)(row0 + r) * F4_PER_ROW + t + NTHREADS * g;
                        float4 v = yo[i];
                        float4 b = ((const float4*)s_b1)[t + NTHREADS * g];
                        v.x = fmaxf((v.x + a) - b.x, 0.f);
                        v.y = fmaxf((v.y + a) - b.y, 0.f);
                        v.z = fmaxf((v.z + a) - b.z, 0.f);
                        v.w = fmaxf((v.w + a) - b.w, 0.f);
                        yo[i] = v;
                    }
                }
            }
        }
        if (t == 0) g_mat = 1;
        return;
    }

    // ---- normal path ----
    const int base = k & ~1;
    const bool two = (k & 1) != 0;        // two levels <=> write pass

    #pragma unroll
    for (int g = 0; g < FPT; g++) {
        int i = t + NTHREADS * g;
        float4 cv = ((const float4*)g_colsum[k])[i];
        ((float4*)s_b1)[i] = make_float4(cv.x * inv_n, cv.y * inv_n,
                                         cv.z * inv_n, cv.w * inv_n);
        if (two) {
            float4 c0 = ((const float4*)g_colsum[base])[i];
            ((float4*)s_b0)[i] = make_float4(c0.x * inv_n, c0.y * inv_n,
                                             c0.z * inv_n, c0.w * inv_n);
        }
    }
    if (t < nrows) {
        float c1 = inv_n + g_total[k] * inv_n * inv_n;
        s_a1[t] = c1 - g_rowsum[k][row0 + t] * inv_n;
        if (two) {
            float c0 = inv_n + g_total[base] * inv_n * inv_n;
            s_a0[t] = c0 - g_rowsum[base][row0 + t] * inv_n;
        }
    }
    __syncthreads();

    const float4* xi = (base == 0) ? (const float4*)X : (const float4*)out;
    float4* yo = (float4*)out;

    float4 cacc[FPT];
    #pragma unroll
    for (int g = 0; g < FPT; g++) cacc[g] = make_float4(0.f, 0.f, 0.f, 0.f);
    bool neg = false;

    #pragma unroll
    for (int r = 0; r < MAXRPB; r++) {
        if (r < nrows) {
            float a1 = s_a1[r];
            float a0 = two ? s_a0[r] : 0.f;
            float rp = 0.f;
            #pragma unroll
            for (int g = 0; g < FPT; g++) {
                int j = t + NTHREADS * g;
                size_t i = (size_t)(row0 + r) * F4_PER_ROW + j;
                float4 v = xi[i];
                if (two) {   // level `base` first (no neg check: set last pass)
                    float4 b0 = ((const float4*)s_b0)[j];
                    v.x = fmaxf((v.x + a0) - b0.x, 0.f);
                    v.y = fmaxf((v.y + a0) - b0.y, 0.f);
                    v.z = fmaxf((v.z + a0) - b0.z, 0.f);
                    v.w = fmaxf((v.w + a0) - b0.w, 0.f);
                }
                float4 b1 = ((const float4*)s_b1)[j];
                float4 xp;
                xp.x = (v.x + a1) - b1.x;
                xp.y = (v.y + a1) - b1.y;
                xp.z = (v.z + a1) - b1.z;
                xp.w = (v.w + a1) - b1.w;
                float mn = fminf(fminf(xp.x, xp.y), fminf(xp.z, xp.w));
                neg = neg || (mn < 0.f);
                float4 y;
                y.x = fmaxf(xp.x, 0.f); y.y = fmaxf(xp.y, 0.f);
                y.z = fmaxf(xp.z, 0.f); y.w = fmaxf(xp.w, 0.f);
                if (two) yo[i] = y;                 // materialize X_{k+1}
                rp += (y.x + y.y) + (y.z + y.w);
                cacc[g].x += y.x; cacc[g].y += y.y; cacc[g].z += y.z; cacc[g].w += y.w;
            }
            float rs = warpReduceSum(rp);
            if (lane == 0) s_part[wid][r] = rs;
        }
    }

    __syncthreads();                    // all s_b0 reads done; s_part ready
    #pragma unroll
    for (int g = 0; g < FPT; g++)
        ((float4*)s_b0)[t + NTHREADS * g] = cacc[g];
    if (t < nrows) {
        float rs = 0.f;
        #pragma unroll
        for (int w = 0; w < NWARPS; w++) rs += s_part[w][t];
        g_rowsum[k + 1][row0 + t] = rs;          // block-exclusive
        atomicAdd(&g_total[k + 1], rs);
    }
    if (__syncthreads_or(neg ? 1 : 0)) {
        if (t == 0) g_neg[k] = 1;
    }
    bulk_reduce_add_f32(&g_colsum[k + 1][0], s_b0);
}

extern "C" void kernel_launch(void* const* d_in, const int* in_sizes, int n_in,
                              void* d_out, int out_size) {
    const float* X = (const float*)d_in[0];
    const int* max_iters = (const int*)d_in[1];
    float* out = (float*)d_out;
    (void)in_sizes; (void)n_in; (void)out_size;

    init_kernel<<<(MAXIT + 1) * F4_PER_ROW / NTHREADS, NTHREADS>>>();  // 84 blocks
    reduce0_kernel<<<NBLK, NTHREADS>>>(X);
    for (int k = 0; k < MAXIT; k++)
        pass_kernel<<<NBLK, NTHREADS>>>(X, out, max_iters, k);
}